// round 3
// baseline (speedup 1.0000x reference)
#include <cuda_runtime.h>

#define TPB 128
#define NH  40
#define NT  40
#define NG  160
#define NC  4

typedef unsigned long long u64;

__device__ __forceinline__ u64 pack2(float lo, float hi) {
    u64 r; asm("mov.b64 %0, {%1, %2};" : "=l"(r) : "f"(lo), "f"(hi)); return r;
}
__device__ __forceinline__ float2 unpack2(u64 v) {
    float2 f; asm("mov.b64 {%0, %1}, %2;" : "=f"(f.x), "=f"(f.y) : "l"(v)); return f;
}
// Packed dual-fp32 FMA (Blackwell f32x2 pipe; 2x fp32 FFMA throughput)
__device__ __forceinline__ u64 ffma2(u64 a, u64 b, u64 c) {
    u64 d; asm("fma.rn.f32x2 %0, %1, %2, %3;" : "=l"(d) : "l"(a), "l"(b), "l"(c)); return d;
}
__device__ __forceinline__ float sigf(float z) {
    return __fdividef(1.0f, 1.0f + __expf(-z));
}
__device__ __forceinline__ float tanh_fast(float z) {
    // tanh(z) = 2*sigmoid(2z) - 1
    return fmaf(2.0f, sigf(2.0f * z), -1.0f);
}

// Compute the 4 gates + cell update for hidden unit j. All W accesses are
// warp-uniform shared-memory broadcasts. 8 independent FFMA2 chains.
__device__ __forceinline__ float lstm_cell(
    int j, float xt, const u64* __restrict__ h2, float* __restrict__ c,
    const float* __restrict__ Ws, const float* __restrict__ win,
    const float* __restrict__ bsum)
{
    const ulonglong2* ri = (const ulonglong2*)(Ws + (size_t)j * NH);
    const ulonglong2* rf = (const ulonglong2*)(Ws + (size_t)(NH + j) * NH);
    const ulonglong2* rg = (const ulonglong2*)(Ws + (size_t)(2 * NH + j) * NH);
    const ulonglong2* ro = (const ulonglong2*)(Ws + (size_t)(3 * NH + j) * NH);

    u64 ai = 0ULL, bi = 0ULL, af = 0ULL, bf = 0ULL;
    u64 ag = 0ULL, bg = 0ULL, ao = 0ULL, bo = 0ULL;
#pragma unroll
    for (int q = 0; q < NH / 4; q++) {
        ulonglong2 wi = ri[q];
        ulonglong2 wf = rf[q];
        ulonglong2 wg = rg[q];
        ulonglong2 wo = ro[q];
        u64 ha = h2[2 * q];
        u64 hb = h2[2 * q + 1];
        ai = ffma2(ha, wi.x, ai); bi = ffma2(hb, wi.y, bi);
        af = ffma2(ha, wf.x, af); bf = ffma2(hb, wf.y, bf);
        ag = ffma2(ha, wg.x, ag); bg = ffma2(hb, wg.y, bg);
        ao = ffma2(ha, wo.x, ao); bo = ffma2(hb, wo.y, bo);
    }
    float2 p, q2;
    p = unpack2(ai); q2 = unpack2(bi);
    float gi = (p.x + p.y) + (q2.x + q2.y) + fmaf(xt, win[j], bsum[j]);
    p = unpack2(af); q2 = unpack2(bf);
    float gf = (p.x + p.y) + (q2.x + q2.y) + fmaf(xt, win[NH + j], bsum[NH + j]);
    p = unpack2(ag); q2 = unpack2(bg);
    float gg = (p.x + p.y) + (q2.x + q2.y) + fmaf(xt, win[2 * NH + j], bsum[2 * NH + j]);
    p = unpack2(ao); q2 = unpack2(bo);
    float go = (p.x + p.y) + (q2.x + q2.y) + fmaf(xt, win[3 * NH + j], bsum[3 * NH + j]);

    float iv = sigf(gi);
    float fv = sigf(gf);
    float gv = tanh_fast(gg);
    float ov = sigf(go);
    float cn = fmaf(fv, c[j], iv * gv);
    c[j] = cn;
    return ov * tanh_fast(cn);
}

__global__ __launch_bounds__(TPB)
void lstm_head_kernel(const float* __restrict__ x,
                      const float* __restrict__ W_ih,
                      const float* __restrict__ W_hh,
                      const float* __restrict__ b_ih,
                      const float* __restrict__ b_hh,
                      const float* __restrict__ W_fc,
                      const float* __restrict__ b_fc,
                      float* __restrict__ out,
                      int write_logits, int write_argmax, long long arg_off)
{
    __shared__ __align__(16) float Ws[NG * NH];      // 25600 B
    __shared__ float win_s[NG];
    __shared__ float b_s[NG];
    __shared__ float Wfc_s[NC * NH];
    __shared__ float bfc_s[NC];
    __shared__ float xs[NT * TPB];                   // 20480 B, [t][thread]

    const int tid = threadIdx.x;
    for (int i = tid; i < NG * NH; i += TPB) Ws[i] = W_hh[i];
    for (int i = tid; i < NG; i += TPB) {
        win_s[i] = W_ih[i];
        b_s[i]   = b_ih[i] + b_hh[i];
    }
    for (int i = tid; i < NC * NH; i += TPB) Wfc_s[i] = W_fc[i];
    if (tid < NC) bfc_s[tid] = b_fc[tid];

    const long long base = (long long)blockIdx.x * TPB;
    // Coalesced global read of this block's x slab, transposed into smem
    for (int i = tid; i < TPB * NT; i += TPB) {
        int s = i / NT;
        int t = i % NT;
        xs[t * TPB + s] = x[(base + s) * NT + t];
    }
    __syncthreads();

    u64 h2[NH / 2];
    float c[NH];
#pragma unroll
    for (int k = 0; k < NH / 2; k++) h2[k] = 0ULL;
#pragma unroll
    for (int j = 0; j < NH; j++) c[j] = 0.0f;

#pragma unroll 1
    for (int t = 0; t < NT; t++) {
        float xt = xs[t * TPB + tid];
        u64 hn[NH / 2];
#pragma unroll 2
        for (int j = 0; j < NH; j += 2) {
            float h0 = lstm_cell(j,     xt, h2, c, Ws, win_s, b_s);
            float h1 = lstm_cell(j + 1, xt, h2, c, Ws, win_s, b_s);
            hn[j >> 1] = pack2(h0, h1);
        }
#pragma unroll
        for (int k = 0; k < NH / 2; k++) h2[k] = hn[k];
    }

    // Final linear head + argmax
    float hT[NH];
#pragma unroll
    for (int k = 0; k < NH / 2; k++) {
        float2 p = unpack2(h2[k]);
        hT[2 * k] = p.x;
        hT[2 * k + 1] = p.y;
    }
    const long long seq = base + tid;
    float best = -3.402823466e38f;
    int bidx = 0;
#pragma unroll
    for (int cls = 0; cls < NC; cls++) {
        float acc = bfc_s[cls];
#pragma unroll
        for (int k = 0; k < NH; k++) acc = fmaf(hT[k], Wfc_s[cls * NH + k], acc);
        if (write_logits) out[seq * NC + cls] = acc;
        if (acc > best) { best = acc; bidx = cls; }
    }
    if (write_argmax) out[arg_off + seq] = (float)bidx;
}

extern "C" void kernel_launch(void* const* d_in, const int* in_sizes, int n_in,
                              void* d_out, int out_size)
{
    const float* x    = (const float*)d_in[0];
    const float* W_ih = (const float*)d_in[1];
    const float* W_hh = (const float*)d_in[2];
    const float* b_ih = (const float*)d_in[3];
    const float* b_hh = (const float*)d_in[4];
    const float* W_fc = (const float*)d_in[5];
    const float* b_fc = (const float*)d_in[6];
    float* out = (float*)d_out;

    const long long B = (long long)in_sizes[0] / NT;

    int write_logits = 1, write_argmax = 0;
    long long arg_off = 0;
    if ((long long)out_size >= B * (NC + 1)) {
        write_logits = 1; write_argmax = 1; arg_off = B * NC;
    } else if ((long long)out_size >= B * NC) {
        write_logits = 1; write_argmax = 0;
    } else {
        // argmax only
        write_logits = 0; write_argmax = 1; arg_off = 0;
    }

    const int grid = (int)((B + TPB - 1) / TPB);
    lstm_head_kernel<<<grid, TPB>>>(x, W_ih, W_hh, b_ih, b_hh, W_fc, b_fc,
                                    out, write_logits, write_argmax, arg_off);
}